// round 1
// baseline (speedup 1.0000x reference)
#include <cuda_runtime.h>
#include <math.h>

#define B 8
#define D 512
#define T 4096
#define CD 64
#define CS 1024
#define NSCALES 4
#define NROWS (B*D)                       // 4096 rows for FFT
#define ZQ_ELEMS (B*D*T)                  // 16777216
#define CODES_ELEMS (B*NSCALES*T)         // 131072
#define LOSS_OFF (ZQ_ELEMS + CODES_ELEMS) // 16908288
#define LOSS_MEAN_DENOM 2097152.0f        // B*CD*T

// ------------------------ scratch (static device memory) ------------------------
__device__ float g_residual[ZQ_ELEMS];        // 64MB
__device__ float g_zf[ZQ_ELEMS];              // 64MB (band-filtered residual)
__device__ float g_ze[B*CD*T];                // 8MB
__device__ float g_Wi[NSCALES*CD*D];          // weight-normed in-proj
__device__ float g_Wo[NSCALES*D*CD];          // weight-normed out-proj
__device__ float g_cn[NSCALES*CS*CD];         // l2-normalized codebook
__device__ float g_cnn[NSCALES*CS];           // ||cn_j||^2 (post-normalization)
__device__ int   g_idx[B*T];                  // codes for current scale
__device__ float g_partials[NSCALES*512];     // per-block loss partial sums

// ------------------------ weight prep (all scales, once) ------------------------
// blocks: per scale, 64 Wi rows (norm over 512), 512 Wo rows (norm over 64),
// 1024 codebook rows (norm over 64).  128 threads/block.
__global__ void prep_weights_kernel(const float* __restrict__ v_in,
                                    const float* __restrict__ g_in,
                                    const float* __restrict__ v_out,
                                    const float* __restrict__ g_out,
                                    const float* __restrict__ codebook)
{
    int blk = blockIdx.x;
    int sc = blk / 1600;
    int r  = blk % 1600;
    int tid = threadIdx.x;
    __shared__ float red[4];

    const float* src; float* dst; int n; float g; bool is_cb = false;
    if (r < 64) {
        src = v_in + (size_t)(sc*64 + r)*512; dst = g_Wi + (size_t)(sc*64 + r)*512;
        n = 512; g = g_in[sc*64 + r];
    } else if (r < 576) {
        int d = r - 64;
        src = v_out + (size_t)(sc*512 + d)*64; dst = g_Wo + (size_t)(sc*512 + d)*64;
        n = 64; g = g_out[sc*512 + d];
    } else {
        int j = r - 576;
        src = codebook + (size_t)(sc*1024 + j)*64; dst = g_cn + (size_t)(sc*1024 + j)*64;
        n = 64; g = 1.0f; is_cb = true;
    }

    float ss = 0.f;
    for (int i = tid; i < n; i += 128) { float v = src[i]; ss = fmaf(v, v, ss); }
    #pragma unroll
    for (int o = 16; o; o >>= 1) ss += __shfl_xor_sync(~0u, ss, o);
    if ((tid & 31) == 0) red[tid >> 5] = ss;
    __syncthreads();
    float tot = red[0] + red[1] + red[2] + red[3];
    float inv = g / fmaxf(sqrtf(tot), 1e-12f);

    float ss2 = 0.f;
    for (int i = tid; i < n; i += 128) { float v = src[i] * inv; dst[i] = v; ss2 = fmaf(v, v, ss2); }
    if (is_cb) {
        #pragma unroll
        for (int o = 16; o; o >>= 1) ss2 += __shfl_xor_sync(~0u, ss2, o);
        __syncthreads();                 // everyone done reading red[] above
        if ((tid & 31) == 0) red[tid >> 5] = ss2;
        __syncthreads();
        if (tid == 0) g_cnn[sc*1024 + (r-576)] = red[0] + red[1] + red[2] + red[3];
    }
}

// ------------------------ FFT band filter ------------------------
// 4096-pt complex FFT per row: forward DIF (natural->bitrev), mask in bitrev
// domain, inverse DIT (bitrev->natural), take real part / N.
__global__ void fft_filter_kernel(const float* __restrict__ zsrc, int use_z, int fl)
{
    __shared__ float2 s[4096];    // 32KB
    __shared__ float2 tw[2048];   // 16KB: tw[k] = exp(-2*pi*i*k/4096)
    const float* src = use_z ? zsrc : g_residual;
    int row = blockIdx.x;
    const float* x = src + (size_t)row * T;
    int tid = threadIdx.x;   // 512

    for (int i = tid; i < 4096; i += 512) s[i] = make_float2(x[i], 0.f);
    for (int k = tid; k < 2048; k += 512) {
        float sv, cv;
        sincospif((float)k * (-1.0f/2048.0f), &sv, &cv);  // exact angle fractions
        tw[k] = make_float2(cv, sv);
    }
    __syncthreads();

    // forward DIF
    for (int logh = 11; logh >= 0; logh--) {
        int h = 1 << logh;
        int tsh = 11 - logh;
        for (int p = tid; p < 2048; p += 512) {
            int j  = p & (h - 1);
            int i0 = ((p >> logh) << (logh + 1)) | j;
            int i1 = i0 + h;
            float2 a = s[i0], bb = s[i1];
            float2 w = tw[j << tsh];
            s[i0] = make_float2(a.x + bb.x, a.y + bb.y);
            float dx = a.x - bb.x, dy = a.y - bb.y;
            s[i1] = make_float2(dx*w.x - dy*w.y, dx*w.y + dy*w.x);
        }
        __syncthreads();
    }

    // mask: element at position p holds X[brev12(p)]; keep k<=fl or k>=4096-fl
    for (int p = tid; p < 4096; p += 512) {
        int k = __brev((unsigned)p) >> 20;
        if (!(k <= fl || k >= 4096 - fl)) s[p] = make_float2(0.f, 0.f);
    }
    __syncthreads();

    // inverse DIT (conjugate twiddles), output natural order
    for (int logh = 0; logh <= 11; logh++) {
        int h = 1 << logh;
        int tsh = 11 - logh;
        for (int p = tid; p < 2048; p += 512) {
            int j  = p & (h - 1);
            int i0 = ((p >> logh) << (logh + 1)) | j;
            int i1 = i0 + h;
            float2 a = s[i0], bb = s[i1];
            float2 w = tw[j << tsh];
            float brx = bb.x*w.x + bb.y*w.y;   // b * conj(w)
            float bry = bb.y*w.x - bb.x*w.y;
            s[i0] = make_float2(a.x + brx, a.y + bry);
            s[i1] = make_float2(a.x - brx, a.y - bry);
        }
        __syncthreads();
    }

    float* y = g_zf + (size_t)row * T;
    const float scl = 1.0f / 4096.0f;
    for (int i = tid; i < 4096; i += 512) y[i] = s[i].x * scl;
}

// ------------------------ in_proj: z_e = Wi @ zf + b_in ------------------------
// grid (T/128, B), 256 threads. Tiled smem GEMM: 64c x 128t output tile.
__global__ void in_proj_kernel(int sc, int use_zf, const float* __restrict__ b_in)
{
    const float* src = use_zf ? g_zf : g_residual;
    const float* Wi = g_Wi + (size_t)sc * CD * D;
    __shared__ float zs[32][128];  // d-chunk x t
    __shared__ float ws[64][32];   // c x d-chunk
    int b = blockIdx.y, t0 = blockIdx.x * 128;
    int tid = threadIdx.x;
    int tx = tid & 31, ty = tid >> 5;   // ty 0..7
    float acc[8][4];
    #pragma unroll
    for (int i = 0; i < 8; i++)
        #pragma unroll
        for (int k = 0; k < 4; k++) acc[i][k] = 0.f;

    const float* zfb = src + (size_t)b * D * T;
    for (int d0 = 0; d0 < D; d0 += 32) {
        for (int i2 = tid; i2 < 32*128; i2 += 256) {
            int dd = i2 >> 7, tt = i2 & 127;
            zs[dd][tt] = zfb[(size_t)(d0 + dd)*T + t0 + tt];
        }
        for (int i2 = tid; i2 < 64*32; i2 += 256) {
            int c = i2 >> 5, dk = i2 & 31;
            ws[c][dk] = Wi[c*D + d0 + dk];
        }
        __syncthreads();
        #pragma unroll
        for (int dd = 0; dd < 32; dd++) {
            float zv[4];
            #pragma unroll
            for (int k = 0; k < 4; k++) zv[k] = zs[dd][tx + 32*k];
            #pragma unroll
            for (int cc = 0; cc < 8; cc++) {
                float wv = ws[ty + 8*cc][dd];
                #pragma unroll
                for (int k = 0; k < 4; k++) acc[cc][k] = fmaf(wv, zv[k], acc[cc][k]);
            }
        }
        __syncthreads();
    }
    #pragma unroll
    for (int cc = 0; cc < 8; cc++) {
        int c = ty + 8*cc;
        float bb = b_in[sc*CD + c];
        #pragma unroll
        for (int k = 0; k < 4; k++)
            g_ze[((size_t)(b*CD + c))*T + t0 + tx + 32*k] = acc[cc][k] + bb;
    }
}

// ------------------------ nearest-code argmax ------------------------
// score_j = 2*(z_e . cn_j)/||z_e|| - ||cn_j||^2  (== -dist up to per-row const)
// grid (T/128, B), 128 threads; each thread owns one t column (z_e in regs).
__global__ void argmax_kernel(int sc, float* __restrict__ codes_out)
{
    __shared__ float4 cs[32][16];   // 32 codes x 64 floats
    __shared__ float  csn[32];
    int b = blockIdx.y;
    int t = blockIdx.x * 128 + threadIdx.x;

    float zev[64];
    float sq = 0.f;
    #pragma unroll
    for (int c = 0; c < 64; c++) {
        float v = g_ze[((size_t)(b*CD + c))*T + t];
        zev[c] = v; sq = fmaf(v, v, sq);
    }
    float inv2 = 2.0f / fmaxf(sqrtf(sq), 1e-12f);

    float best = -INFINITY; int bi = 0;
    const float4* cn = (const float4*)(g_cn + (size_t)sc * CS * CD);
    const float*  cnn = g_cnn + sc * CS;
    for (int j0 = 0; j0 < CS; j0 += 32) {
        __syncthreads();
        for (int l = threadIdx.x; l < 512; l += 128) cs[l >> 4][l & 15] = cn[j0*16 + l];
        if (threadIdx.x < 32) csn[threadIdx.x] = cnn[j0 + threadIdx.x];
        __syncthreads();
        for (int jj = 0; jj < 32; jj++) {
            float dot = 0.f;
            #pragma unroll
            for (int q = 0; q < 16; q++) {
                float4 w = cs[jj][q];
                dot = fmaf(w.x, zev[4*q+0], dot);
                dot = fmaf(w.y, zev[4*q+1], dot);
                dot = fmaf(w.z, zev[4*q+2], dot);
                dot = fmaf(w.w, zev[4*q+3], dot);
            }
            float score = fmaf(dot, inv2, -csn[jj]);
            if (score > best) { best = score; bi = j0 + jj; }   // first-index tie-break
        }
    }
    g_idx[b*T + t] = bi;
    if (codes_out) codes_out[((size_t)(b*NSCALES + sc))*T + t] = (float)bi;
}

// ------------------------ loss + out_proj + residual update ------------------------
// mode 0: residual = z - v     (first scale)
// mode 1: residual -= v        (middle scales)
// mode 2: zq_out = z - residual + v  (last scale; no residual write)
__global__ void loss_outproj_kernel(int sc, int mode,
    const float* __restrict__ cb_s, const float* __restrict__ b_out_s,
    const float* __restrict__ z, float* __restrict__ zq_out)
{
    __shared__ float cbs[64][65];   // [c][t], padded
    __shared__ float wos[64][64];   // [dd][c]
    __shared__ int   codes_s[64];
    __shared__ float red[8];
    int b = blockIdx.y, t0 = blockIdx.x * 64;
    int tid = threadIdx.x;

    if (tid < 64) codes_s[tid] = g_idx[b*T + t0 + tid];
    __syncthreads();
    // gather codebook vectors (coalesced over c)
    for (int i = tid; i < 4096; i += 256) {
        int tt = i >> 6, c = i & 63;
        cbs[c][tt] = cb_s[codes_s[tt]*64 + c];
    }
    __syncthreads();
    // loss: sum (z_e - cb)^2  (coalesced z_e reads over t)
    float ls = 0.f;
    for (int i = tid; i < 4096; i += 256) {
        int c = i >> 6, tt = i & 63;
        float d = g_ze[((size_t)(b*CD + c))*T + t0 + tt] - cbs[c][tt];
        ls = fmaf(d, d, ls);
    }
    #pragma unroll
    for (int o = 16; o; o >>= 1) ls += __shfl_xor_sync(~0u, ls, o);
    if ((tid & 31) == 0) red[tid >> 5] = ls;
    __syncthreads();
    if (tid == 0) {
        float tot = 0.f;
        #pragma unroll
        for (int w = 0; w < 8; w++) tot += red[w];
        g_partials[sc*512 + b*64 + blockIdx.x] = tot;
    }

    // out_proj: v[d,t] = Wo[d,:] . cb[:,t] + b_out[d]
    int tx = tid & 31, ty = tid >> 5;
    for (int d0 = 0; d0 < D; d0 += 64) {
        __syncthreads();
        for (int i = tid; i < 4096; i += 256) {
            int dd = i >> 6, c = i & 63;
            wos[dd][c] = g_Wo[(size_t)sc*D*CD + (d0 + dd)*64 + c];
        }
        __syncthreads();
        float a0[8], a1[8];
        #pragma unroll
        for (int k = 0; k < 8; k++) { a0[k] = 0.f; a1[k] = 0.f; }
        #pragma unroll
        for (int c = 0; c < 64; c++) {
            float cv0 = cbs[c][tx], cv1 = cbs[c][tx + 32];
            #pragma unroll
            for (int k = 0; k < 8; k++) {
                float wv = wos[ty + 8*k][c];
                a0[k] = fmaf(wv, cv0, a0[k]);
                a1[k] = fmaf(wv, cv1, a1[k]);
            }
        }
        #pragma unroll
        for (int k = 0; k < 8; k++) {
            int d = d0 + ty + 8*k;
            float bb = b_out_s[d];
            size_t base = ((size_t)(b*D + d))*T + t0;
            float v0 = a0[k] + bb, v1 = a1[k] + bb;
            if (mode == 0) {
                g_residual[base + tx]      = z[base + tx]      - v0;
                g_residual[base + tx + 32] = z[base + tx + 32] - v1;
            } else if (mode == 1) {
                g_residual[base + tx]      -= v0;
                g_residual[base + tx + 32] -= v1;
            } else {
                zq_out[base + tx]      = z[base + tx]      - g_residual[base + tx]      + v0;
                zq_out[base + tx + 32] = z[base + tx + 32] - g_residual[base + tx + 32] + v1;
            }
        }
    }
}

// ------------------------ final deterministic loss reduce ------------------------
__global__ void reduce_loss_kernel(float* __restrict__ out_loss)
{
    __shared__ float s[1024];
    int tid = threadIdx.x;
    float v = 0.f;
    for (int i = tid; i < NSCALES*512; i += 1024) v += g_partials[i];
    s[tid] = v;
    __syncthreads();
    for (int h = 512; h; h >>= 1) {
        if (tid < h) s[tid] += s[tid + h];
        __syncthreads();
    }
    if (tid == 0) {
        float m = s[0] / LOSS_MEAN_DENOM;
        out_loss[0] = m;   // commitment_loss
        out_loss[1] = m;   // codebook_loss (identical in value)
    }
}

// ------------------------ launch ------------------------
extern "C" void kernel_launch(void* const* d_in, const int* in_sizes, int n_in,
                              void* d_out, int out_size)
{
    const float* z     = (const float*)d_in[0];
    const float* v_in  = (const float*)d_in[1];
    const float* g_in  = (const float*)d_in[2];
    const float* b_in  = (const float*)d_in[3];
    const float* cb    = (const float*)d_in[4];
    const float* v_out = (const float*)d_in[5];
    const float* g_out = (const float*)d_in[6];
    const float* b_out = (const float*)d_in[7];
    float* out = (float*)d_out;

    bool full = out_size >= (LOSS_OFF + 2);
    float* codes_out = full ? (out + ZQ_ELEMS) : nullptr;

    prep_weights_kernel<<<NSCALES*1600, 128>>>(v_in, g_in, v_out, g_out, cb);

    const int scales[NSCALES] = {4, 2, 1, 1};
    for (int i = 0; i < NSCALES; i++) {
        int s = scales[i];
        int use_zf = (s > 1) ? 1 : 0;
        if (use_zf) {
            int fl = 2049 / s;   // (T/2+1)//scale
            fft_filter_kernel<<<NROWS, 512>>>(z, (i == 0) ? 1 : 0, fl);
        }
        in_proj_kernel<<<dim3(T/128, B), 256>>>(i, use_zf, b_in);
        argmax_kernel<<<dim3(T/128, B), 128>>>(i, codes_out);
        int mode = (i == 0) ? 0 : ((i == NSCALES-1) ? 2 : 1);
        loss_outproj_kernel<<<dim3(T/64, B), 256>>>(i, mode, cb + (size_t)i*CS*CD,
                                                    b_out + i*D, z, out);
    }
    if (full) reduce_loss_kernel<<<1, 1024>>>(out + LOSS_OFF);
}

// round 2
// speedup vs baseline: 1.6174x; 1.6174x over previous
#include <cuda_runtime.h>
#include <math.h>

#define B 8
#define D 512
#define T 4096
#define CD 64
#define CS 1024
#define NSCALES 4
#define NSPLIT 8
#define NROWS (B*D)                       // 4096 rows for FFT
#define ZQ_ELEMS (B*D*T)                  // 16777216
#define CODES_ELEMS (B*NSCALES*T)         // 131072
#define LOSS_OFF (ZQ_ELEMS + CODES_ELEMS) // 16908288
#define LOSS_MEAN_DENOM 2097152.0f        // B*CD*T

// ------------------------ scratch (static device memory) ------------------------
__device__ float g_residual[ZQ_ELEMS];        // 64MB
__device__ float g_zf[ZQ_ELEMS];              // 64MB (band-filtered residual)
__device__ float g_ze[B*CD*T];                // 8MB
__device__ float g_Wi[NSCALES*CD*D];          // weight-normed in-proj
__device__ float g_Wo[NSCALES*D*CD];          // weight-normed out-proj
__device__ float g_cnp[NSCALES*CS*CD];        // normalized codebook, transposed/packed
__device__ float g_cnn[NSCALES*CS];           // ||cn_j||^2 (post-normalization)
__device__ int   g_idx[B*T];                  // codes for current scale
__device__ float g_pbest[NSPLIT*B*T];         // per-split argmax partials
__device__ int   g_pidx [NSPLIT*B*T];
__device__ float g_partials[NSCALES*512];     // per-block loss partial sums

// ------------------------ f32x2 helpers ------------------------
__device__ __forceinline__ void fma2(unsigned long long& acc,
                                     unsigned long long a, unsigned long long b) {
    asm("fma.rn.f32x2 %0, %1, %2, %0;" : "+l"(acc) : "l"(a), "l"(b));
}
__device__ __forceinline__ unsigned long long packf2(float lo, float hi) {
    unsigned long long r;
    asm("mov.b64 %0, {%1, %2};" : "=l"(r) : "f"(lo), "f"(hi));
    return r;
}
__device__ __forceinline__ float2 unpackf2(unsigned long long v) {
    float lo, hi;
    asm("mov.b64 {%0, %1}, %2;" : "=f"(lo), "=f"(hi) : "l"(v));
    return make_float2(lo, hi);
}

// ------------------------ complex helpers ------------------------
__device__ __forceinline__ float2 cadd(float2 a, float2 b){return make_float2(a.x+b.x, a.y+b.y);}
__device__ __forceinline__ float2 csub(float2 a, float2 b){return make_float2(a.x-b.x, a.y-b.y);}
__device__ __forceinline__ float2 cmul(float2 a, float2 b){
    return make_float2(a.x*b.x - a.y*b.y, a.x*b.y + a.y*b.x);}
__device__ __forceinline__ float2 cmulc(float2 a, float2 b){   // a * conj(b)
    return make_float2(a.x*b.x + a.y*b.y, a.y*b.x - a.x*b.y);}
__device__ __forceinline__ float2 mulnegi(float2 a){return make_float2(a.y, -a.x);}  // a * -i
__device__ __forceinline__ float2 mulposi(float2 a){return make_float2(-a.y, a.x);}  // a *  i

// ------------------------ weight prep (all scales, once) ------------------------
// blocks per scale: 64 Wi rows, 512 Wo rows, 1024 codebook rows. 128 threads.
// Codebook rows are written normalized into a transposed, pair-packed layout:
// float index = (((sc*32 + j/32)*64 + c)*8 + (j%32)/4)*4 + (j%4)
__global__ void prep_weights_kernel(const float* __restrict__ v_in,
                                    const float* __restrict__ g_in,
                                    const float* __restrict__ v_out,
                                    const float* __restrict__ g_out,
                                    const float* __restrict__ codebook)
{
    int blk = blockIdx.x;
    int sc = blk / 1600;
    int r  = blk % 1600;
    int tid = threadIdx.x;
    __shared__ float red[4];

    const float* src; float* dst = nullptr; int n; float g; bool is_cb = false;
    if (r < 64) {
        src = v_in + (size_t)(sc*64 + r)*512; dst = g_Wi + (size_t)(sc*64 + r)*512;
        n = 512; g = g_in[sc*64 + r];
    } else if (r < 576) {
        int d = r - 64;
        src = v_out + (size_t)(sc*512 + d)*64; dst = g_Wo + (size_t)(sc*512 + d)*64;
        n = 64; g = g_out[sc*512 + d];
    } else {
        int j = r - 576;
        src = codebook + (size_t)(sc*1024 + j)*64;
        n = 64; g = 1.0f; is_cb = true;
    }

    float ss = 0.f;
    for (int i = tid; i < n; i += 128) { float v = src[i]; ss = fmaf(v, v, ss); }
    #pragma unroll
    for (int o = 16; o; o >>= 1) ss += __shfl_xor_sync(~0u, ss, o);
    if ((tid & 31) == 0) red[tid >> 5] = ss;
    __syncthreads();
    float tot = red[0] + red[1] + red[2] + red[3];
    float inv = g / fmaxf(sqrtf(tot), 1e-12f);

    float ss2 = 0.f;
    if (is_cb) {
        int j = r - 576;
        for (int i = tid; i < n; i += 128) {
            float v = src[i] * inv;
            size_t fidx = ((((size_t)(sc*32 + (j>>5))*64 + i)*8 + ((j&31)>>2))*4) + (j&3);
            g_cnp[fidx] = v;
            ss2 = fmaf(v, v, ss2);
        }
        #pragma unroll
        for (int o = 16; o; o >>= 1) ss2 += __shfl_xor_sync(~0u, ss2, o);
        __syncthreads();
        if ((tid & 31) == 0) red[tid >> 5] = ss2;
        __syncthreads();
        if (tid == 0) g_cnn[sc*1024 + j] = red[0] + red[1] + red[2] + red[3];
    } else {
        for (int i = tid; i < n; i += 128) dst[i] = src[i] * inv;
    }
}

// ------------------------ FFT band filter (radix-4, 2 packed real rows) ------------------------
// Two real rows packed as re+im of one 4096-pt complex FFT. The band mask is
// conjugate-symmetric, so masking the packed spectrum filters both rows.
// Forward radix-4 DIF (natural -> base4-digit-reversed), mask, inverse radix-4
// DIT (digit-reversed -> natural). Output re/N, im/N to the two rows.
__global__ void fft_filter_kernel(const float* __restrict__ zsrc, int use_z, int fl)
{
    __shared__ float2 s[4096];    // 32KB
    __shared__ float2 tw[2048];   // 16KB : tw[k] = exp(-2*pi*i*k/4096)
    const float* src = use_z ? zsrc : g_residual;
    size_t roff = (size_t)blockIdx.x * 2 * T;
    const float* x0 = src + roff;
    const float* x1 = x0 + T;
    int tid = threadIdx.x;   // 512

    for (int i = tid; i < 4096; i += 512) s[i] = make_float2(x0[i], x1[i]);
    for (int k = tid; k < 2048; k += 512) {
        float sv, cv;
        sincospif((float)k * (-1.0f/2048.0f), &sv, &cv);
        tw[k] = make_float2(cv, sv);
    }
    __syncthreads();

    // forward radix-4 DIF: q = 1024, 256, 64, 16, 4, 1
    for (int logq = 10; logq >= 0; logq -= 2) {
        int q = 1 << logq;
        int tsh = 10 - logq;
        #pragma unroll
        for (int pp = 0; pp < 2; pp++) {
            int p = tid + pp*512;
            int j = p & (q - 1);
            int base = ((p >> logq) << (logq + 2)) | j;
            float2 a = s[base], b = s[base+q], c = s[base+2*q], d = s[base+3*q];
            float2 t0 = cadd(a, c), t1 = csub(a, c);
            float2 t2 = cadd(b, d), t3 = mulnegi(csub(b, d));
            int jt = j << tsh;               // jt < 1024
            float2 w1 = tw[jt];
            float2 w2 = tw[2*jt];
            float2 w3 = cmul(w1, w2);
            s[base]       = cadd(t0, t2);
            s[base+q]     = cmul(cadd(t1, t3), w1);
            s[base+2*q]   = cmul(csub(t0, t2), w2);
            s[base+3*q]   = cmul(csub(t1, t3), w3);
        }
        __syncthreads();
    }

    // mask: position p holds X[k], k = base-4 digit reversal of p
    for (int p = tid; p < 4096; p += 512) {
        unsigned rb = __brev((unsigned)p) >> 20;
        int k = (int)(((rb & 0x555u) << 1) | ((rb >> 1) & 0x555u));
        if (!(k <= fl || k >= 4096 - fl)) s[p] = make_float2(0.f, 0.f);
    }
    __syncthreads();

    // inverse radix-4 DIT: q = 1, 4, 16, 64, 256, 1024
    for (int logq = 0; logq <= 10; logq += 2) {
        int q = 1 << logq;
        int tsh = 10 - logq;
        #pragma unroll
        for (int pp = 0; pp < 2; pp++) {
            int p = tid + pp*512;
            int j = p & (q - 1);
            int base = ((p >> logq) << (logq + 2)) | j;
            int jt = j << tsh;
            float2 w1 = tw[jt];
            float2 w2 = tw[2*jt];
            float2 w3 = cmul(w1, w2);
            float2 a = s[base];
            float2 b = cmulc(s[base+q],   w1);
            float2 c = cmulc(s[base+2*q], w2);
            float2 d = cmulc(s[base+3*q], w3);
            float2 t0 = cadd(a, c), t1 = csub(a, c);
            float2 t2 = cadd(b, d), t3 = mulposi(csub(b, d));
            s[base]     = cadd(t0, t2);
            s[base+q]   = cadd(t1, t3);
            s[base+2*q] = csub(t0, t2);
            s[base+3*q] = csub(t1, t3);
        }
        __syncthreads();
    }

    float* y0 = g_zf + roff;
    float* y1 = y0 + T;
    const float scl = 1.0f / 4096.0f;
    for (int i = tid; i < 4096; i += 512) {
        float2 v = s[i];
        y0[i] = v.x * scl;
        y1[i] = v.y * scl;
    }
}

// ------------------------ in_proj: z_e = Wi @ zf + b_in ------------------------
__global__ void in_proj_kernel(int sc, int use_zf, const float* __restrict__ b_in)
{
    const float* src = use_zf ? g_zf : g_residual;
    const float* Wi = g_Wi + (size_t)sc * CD * D;
    __shared__ float zs[32][128];
    __shared__ float ws[64][32];
    int b = blockIdx.y, t0 = blockIdx.x * 128;
    int tid = threadIdx.x;
    int tx = tid & 31, ty = tid >> 5;
    float acc[8][4];
    #pragma unroll
    for (int i = 0; i < 8; i++)
        #pragma unroll
        for (int k = 0; k < 4; k++) acc[i][k] = 0.f;

    const float* zfb = src + (size_t)b * D * T;
    for (int d0 = 0; d0 < D; d0 += 32) {
        for (int i2 = tid; i2 < 32*128; i2 += 256) {
            int dd = i2 >> 7, tt = i2 & 127;
            zs[dd][tt] = zfb[(size_t)(d0 + dd)*T + t0 + tt];
        }
        for (int i2 = tid; i2 < 64*32; i2 += 256) {
            int c = i2 >> 5, dk = i2 & 31;
            ws[c][dk] = Wi[c*D + d0 + dk];
        }
        __syncthreads();
        #pragma unroll
        for (int dd = 0; dd < 32; dd++) {
            float zv[4];
            #pragma unroll
            for (int k = 0; k < 4; k++) zv[k] = zs[dd][tx + 32*k];
            #pragma unroll
            for (int cc = 0; cc < 8; cc++) {
                float wv = ws[ty + 8*cc][dd];
                #pragma unroll
                for (int k = 0; k < 4; k++) acc[cc][k] = fmaf(wv, zv[k], acc[cc][k]);
            }
        }
        __syncthreads();
    }
    #pragma unroll
    for (int cc = 0; cc < 8; cc++) {
        int c = ty + 8*cc;
        float bb = b_in[sc*CD + c];
        #pragma unroll
        for (int k = 0; k < 4; k++)
            g_ze[((size_t)(b*CD + c))*T + t0 + tx + 32*k] = acc[cc][k] + bb;
    }
}

// ------------------------ nearest-code argmax (f32x2, code-split) ------------------------
// grid (T/128, B, NSPLIT); 128 threads. Each block handles 128 t-columns and a
// 128-code range (4 tiles of 32). Scores accumulated pairwise with fma.rn.f32x2.
__global__ void argmax_kernel(int sc)
{
    __shared__ ulonglong2 cs2[64][8];   // [c][code-quad] : packed pairs
    __shared__ float csn[32];
    int b = blockIdx.y, split = blockIdx.z;
    int t = blockIdx.x * 128 + threadIdx.x;

    float zev[64];
    float sq = 0.f;
    #pragma unroll
    for (int c = 0; c < 64; c++) {
        float v = g_ze[((size_t)(b*CD + c))*T + t];
        zev[c] = v; sq = fmaf(v, v, sq);
    }
    float inv2 = 2.0f / fmaxf(sqrtf(sq), 1e-12f);

    float best = -INFINITY; int bi = 0;
    for (int tt = 0; tt < 4; tt++) {
        int tileIdx = split*4 + tt;
        __syncthreads();
        const float4* p = (const float4*)(g_cnp + (size_t)(sc*32 + tileIdx)*2048);
        for (int l = threadIdx.x; l < 512; l += 128) ((float4*)cs2)[l] = p[l];
        if (threadIdx.x < 32) csn[threadIdx.x] = g_cnn[sc*CS + tileIdx*32 + threadIdx.x];
        __syncthreads();

        unsigned long long acc[16];
        #pragma unroll
        for (int m = 0; m < 16; m++) acc[m] = 0ull;
        #pragma unroll 8
        for (int c = 0; c < 64; c++) {
            unsigned long long zz = packf2(zev[c], zev[c]);
            #pragma unroll
            for (int m = 0; m < 8; m++) {
                ulonglong2 w = cs2[c][m];
                fma2(acc[2*m],   w.x, zz);
                fma2(acc[2*m+1], w.y, zz);
            }
        }
        #pragma unroll
        for (int m = 0; m < 16; m++) {
            float2 dd = unpackf2(acc[m]);
            float s0 = fmaf(dd.x, inv2, -csn[2*m]);
            float s1 = fmaf(dd.y, inv2, -csn[2*m+1]);
            int j0 = tileIdx*32 + 2*m;
            if (s0 > best) { best = s0; bi = j0; }
            if (s1 > best) { best = s1; bi = j0 + 1; }
        }
    }
    int gi = b*T + t;
    g_pbest[split*(B*T) + gi] = best;
    g_pidx [split*(B*T) + gi] = bi;
}

// ------------------------ argmax combine over splits ------------------------
__global__ void argmax_combine_kernel(int sc, float* __restrict__ codes_out)
{
    int i = blockIdx.x * 256 + threadIdx.x;   // i = b*T + t
    float best = -INFINITY; int bi = 0;
    #pragma unroll
    for (int sp = 0; sp < NSPLIT; sp++) {     // ascending splits = ascending codes
        float v = g_pbest[sp*(B*T) + i];
        int ix = g_pidx[sp*(B*T) + i];
        if (v > best) { best = v; bi = ix; }
    }
    g_idx[i] = bi;
    if (codes_out) {
        int b = i >> 12, t = i & (T-1);
        codes_out[((size_t)(b*NSCALES + sc))*T + t] = (float)bi;
    }
}

// ------------------------ loss + out_proj + residual update ------------------------
__global__ void loss_outproj_kernel(int sc, int mode,
    const float* __restrict__ cb_s, const float* __restrict__ b_out_s,
    const float* __restrict__ z, float* __restrict__ zq_out)
{
    __shared__ float cbs[64][65];
    __shared__ float wos[64][64];
    __shared__ int   codes_s[64];
    __shared__ float red[8];
    int b = blockIdx.y, t0 = blockIdx.x * 64;
    int tid = threadIdx.x;

    if (tid < 64) codes_s[tid] = g_idx[b*T + t0 + tid];
    __syncthreads();
    for (int i = tid; i < 4096; i += 256) {
        int tt = i >> 6, c = i & 63;
        cbs[c][tt] = cb_s[codes_s[tt]*64 + c];
    }
    __syncthreads();
    float ls = 0.f;
    for (int i = tid; i < 4096; i += 256) {
        int c = i >> 6, tt = i & 63;
        float d = g_ze[((size_t)(b*CD + c))*T + t0 + tt] - cbs[c][tt];
        ls = fmaf(d, d, ls);
    }
    #pragma unroll
    for (int o = 16; o; o >>= 1) ls += __shfl_xor_sync(~0u, ls, o);
    if ((tid & 31) == 0) red[tid >> 5] = ls;
    __syncthreads();
    if (tid == 0) {
        float tot = 0.f;
        #pragma unroll
        for (int w = 0; w < 8; w++) tot += red[w];
        g_partials[sc*512 + b*64 + blockIdx.x] = tot;
    }

    int tx = tid & 31, ty = tid >> 5;
    for (int d0 = 0; d0 < D; d0 += 64) {
        __syncthreads();
        for (int i = tid; i < 4096; i += 256) {
            int dd = i >> 6, c = i & 63;
            wos[dd][c] = g_Wo[(size_t)sc*D*CD + (d0 + dd)*64 + c];
        }
        __syncthreads();
        float a0[8], a1[8];
        #pragma unroll
        for (int k = 0; k < 8; k++) { a0[k] = 0.f; a1[k] = 0.f; }
        #pragma unroll
        for (int c = 0; c < 64; c++) {
            float cv0 = cbs[c][tx], cv1 = cbs[c][tx + 32];
            #pragma unroll
            for (int k = 0; k < 8; k++) {
                float wv = wos[ty + 8*k][c];
                a0[k] = fmaf(wv, cv0, a0[k]);
                a1[k] = fmaf(wv, cv1, a1[k]);
            }
        }
        #pragma unroll
        for (int k = 0; k < 8; k++) {
            int d = d0 + ty + 8*k;
            float bb = b_out_s[d];
            size_t base = ((size_t)(b*D + d))*T + t0;
            float v0 = a0[k] + bb, v1 = a1[k] + bb;
            if (mode == 0) {
                g_residual[base + tx]      = z[base + tx]      - v0;
                g_residual[base + tx + 32] = z[base + tx + 32] - v1;
            } else if (mode == 1) {
                g_residual[base + tx]      -= v0;
                g_residual[base + tx + 32] -= v1;
            } else {
                zq_out[base + tx]      = z[base + tx]      - g_residual[base + tx]      + v0;
                zq_out[base + tx + 32] = z[base + tx + 32] - g_residual[base + tx + 32] + v1;
            }
        }
    }
}

// ------------------------ final deterministic loss reduce ------------------------
__global__ void reduce_loss_kernel(float* __restrict__ out_loss)
{
    __shared__ float s[1024];
    int tid = threadIdx.x;
    float v = 0.f;
    for (int i = tid; i < NSCALES*512; i += 1024) v += g_partials[i];
    s[tid] = v;
    __syncthreads();
    for (int h = 512; h; h >>= 1) {
        if (tid < h) s[tid] += s[tid + h];
        __syncthreads();
    }
    if (tid == 0) {
        float m = s[0] / LOSS_MEAN_DENOM;
        out_loss[0] = m;
        out_loss[1] = m;
    }
}

// ------------------------ launch ------------------------
extern "C" void kernel_launch(void* const* d_in, const int* in_sizes, int n_in,
                              void* d_out, int out_size)
{
    const float* z     = (const float*)d_in[0];
    const float* v_in  = (const float*)d_in[1];
    const float* g_in  = (const float*)d_in[2];
    const float* b_in  = (const float*)d_in[3];
    const float* cb    = (const float*)d_in[4];
    const float* v_out = (const float*)d_in[5];
    const float* g_out = (const float*)d_in[6];
    const float* b_out = (const float*)d_in[7];
    float* out = (float*)d_out;

    bool full = out_size >= (LOSS_OFF + 2);
    float* codes_out = full ? (out + ZQ_ELEMS) : nullptr;

    prep_weights_kernel<<<NSCALES*1600, 128>>>(v_in, g_in, v_out, g_out, cb);

    const int scales[NSCALES] = {4, 2, 1, 1};
    for (int i = 0; i < NSCALES; i++) {
        int s = scales[i];
        int use_zf = (s > 1) ? 1 : 0;
        if (use_zf) {
            int fl = 2049 / s;
            fft_filter_kernel<<<NROWS/2, 512>>>(z, (i == 0) ? 1 : 0, fl);
        }
        in_proj_kernel<<<dim3(T/128, B), 256>>>(i, use_zf, b_in);
        argmax_kernel<<<dim3(T/128, B, NSPLIT), 128>>>(i);
        argmax_combine_kernel<<<(B*T)/256, 256>>>(i, codes_out);
        int mode = (i == 0) ? 0 : ((i == NSCALES-1) ? 2 : 1);
        loss_outproj_kernel<<<dim3(T/64, B), 256>>>(i, mode, cb + (size_t)i*CS*CD,
                                                    b_out + i*D, z, out);
    }
    if (full) reduce_loss_kernel<<<1, 1024>>>(out + LOSS_OFF);
}

// round 3
// speedup vs baseline: 2.0157x; 1.2463x over previous
#include <cuda_runtime.h>
#include <math.h>

#define B 8
#define D 512
#define T 4096
#define CD 64
#define CS 1024
#define NSCALES 4
#define NSPLIT 16
#define NROWS (B*D)
#define BT (B*T)
#define ZQ_ELEMS (B*D*T)                  // 16777216
#define CODES_ELEMS (B*NSCALES*T)         // 131072
#define LOSS_OFF (ZQ_ELEMS + CODES_ELEMS)
#define LOSS_MEAN_DENOM 2097152.0f        // B*CD*T

// ------------------------ scratch ------------------------
__device__ float g_residual[ZQ_ELEMS];        // 64MB
__device__ float g_zf[ZQ_ELEMS];              // 64MB
__device__ float g_ze[B*CD*T];                // 8MB
__device__ float g_inv2[BT];                  // 2/||z_e(t)||
__device__ float g_WiT[NSCALES*D*CD];         // weight-normed in-proj, [d][c]
__device__ float g_WoT[NSCALES*CD*D];         // weight-normed out-proj, [c][d]
__device__ float g_cnp[NSCALES*CS*CD];        // normalized codebook, tile/pair-packed
__device__ float g_cnn[NSCALES*CS];           // ||cn_j||^2
__device__ float g_pbest[NSPLIT*BT];
__device__ int   g_pidx [NSPLIT*BT];
__device__ float g_partials[NSCALES*256];

// ------------------------ f32x2 helpers ------------------------
__device__ __forceinline__ void fma2(unsigned long long& acc,
                                     unsigned long long a, unsigned long long b) {
    asm("fma.rn.f32x2 %0, %1, %2, %0;" : "+l"(acc) : "l"(a), "l"(b));
}
__device__ __forceinline__ unsigned long long packf2(float lo, float hi) {
    unsigned long long r;
    asm("mov.b64 %0, {%1, %2};" : "=l"(r) : "f"(lo), "f"(hi));
    return r;
}
__device__ __forceinline__ float2 unpackf2(unsigned long long v) {
    float lo, hi;
    asm("mov.b64 {%0, %1}, %2;" : "=f"(lo), "=f"(hi) : "l"(v));
    return make_float2(lo, hi);
}

// ------------------------ complex helpers ------------------------
__device__ __forceinline__ float2 cadd(float2 a, float2 b){return make_float2(a.x+b.x, a.y+b.y);}
__device__ __forceinline__ float2 csub(float2 a, float2 b){return make_float2(a.x-b.x, a.y-b.y);}
__device__ __forceinline__ float2 cmul(float2 a, float2 b){
    return make_float2(a.x*b.x - a.y*b.y, a.x*b.y + a.y*b.x);}
__device__ __forceinline__ float2 cmulc(float2 a, float2 b){
    return make_float2(a.x*b.x + a.y*b.y, a.y*b.x - a.x*b.y);}
__device__ __forceinline__ float2 mulnegi(float2 a){return make_float2(a.y, -a.x);}
__device__ __forceinline__ float2 mulposi(float2 a){return make_float2(-a.y, a.x);}

// ------------------------ weight prep ------------------------
// Wi row c -> g_WiT[d][c]; Wo row d -> g_WoT[c][d]; codebook row j -> packed tiles.
__global__ void prep_weights_kernel(const float* __restrict__ v_in,
                                    const float* __restrict__ g_in,
                                    const float* __restrict__ v_out,
                                    const float* __restrict__ g_out,
                                    const float* __restrict__ codebook)
{
    int blk = blockIdx.x;
    int sc = blk / 1600;
    int r  = blk % 1600;
    int tid = threadIdx.x;
    __shared__ float red[4];

    const float* src; int n; float g; int kind;
    if (r < 64) { src = v_in + (size_t)(sc*64 + r)*512; n = 512; g = g_in[sc*64 + r]; kind = 0; }
    else if (r < 576) { int d = r-64; src = v_out + (size_t)(sc*512 + d)*64; n = 64; g = g_out[sc*512 + d]; kind = 1; }
    else { src = codebook + (size_t)(sc*1024 + (r-576))*64; n = 64; g = 1.0f; kind = 2; }

    float ss = 0.f;
    for (int i = tid; i < n; i += 128) { float v = src[i]; ss = fmaf(v, v, ss); }
    #pragma unroll
    for (int o = 16; o; o >>= 1) ss += __shfl_xor_sync(~0u, ss, o);
    if ((tid & 31) == 0) red[tid >> 5] = ss;
    __syncthreads();
    float tot = red[0] + red[1] + red[2] + red[3];
    float inv = g / fmaxf(sqrtf(tot), 1e-12f);

    if (kind == 0) {
        int c = r;
        for (int i = tid; i < n; i += 128)
            g_WiT[((size_t)sc*512 + i)*64 + c] = src[i] * inv;
    } else if (kind == 1) {
        int d = r - 64;
        for (int i = tid; i < n; i += 128)
            g_WoT[((size_t)sc*64 + i)*512 + d] = src[i] * inv;
    } else {
        int j = r - 576;
        float ss2 = 0.f;
        for (int i = tid; i < n; i += 128) {
            float v = src[i] * inv;
            // tile = j/32, within-tile layout [c][quad j%32/4][j%4]
            size_t fidx = ((((size_t)(sc*32 + (j>>5))*64 + i)*8 + ((j&31)>>2))*4) + (j&3);
            g_cnp[fidx] = v;
            ss2 = fmaf(v, v, ss2);
        }
        #pragma unroll
        for (int o = 16; o; o >>= 1) ss2 += __shfl_xor_sync(~0u, ss2, o);
        __syncthreads();
        if ((tid & 31) == 0) red[tid >> 5] = ss2;
        __syncthreads();
        if (tid == 0) g_cnn[sc*1024 + j] = red[0] + red[1] + red[2] + red[3];
    }
}

// ------------------------ FFT band filter (radix-4, 2 packed real rows) ------------------------
__global__ __launch_bounds__(512) void fft_filter_kernel(const float* __restrict__ zsrc, int use_z, int fl)
{
    __shared__ float2 s[4096];
    __shared__ float2 tw[2048];
    const float* src = use_z ? zsrc : g_residual;
    size_t roff = (size_t)blockIdx.x * 2 * T;
    const float* x0 = src + roff;
    const float* x1 = x0 + T;
    int tid = threadIdx.x;

    for (int i = tid; i < 4096; i += 512) s[i] = make_float2(x0[i], x1[i]);
    for (int k = tid; k < 2048; k += 512) {
        float sv, cv;
        sincospif((float)k * (-1.0f/2048.0f), &sv, &cv);
        tw[k] = make_float2(cv, sv);
    }
    __syncthreads();

    for (int logq = 10; logq >= 0; logq -= 2) {
        int q = 1 << logq;
        int tsh = 10 - logq;
        #pragma unroll
        for (int pp = 0; pp < 2; pp++) {
            int p = tid + pp*512;
            int j = p & (q - 1);
            int base = ((p >> logq) << (logq + 2)) | j;
            float2 a = s[base], b = s[base+q], c = s[base+2*q], d = s[base+3*q];
            float2 t0 = cadd(a, c), t1 = csub(a, c);
            float2 t2 = cadd(b, d), t3 = mulnegi(csub(b, d));
            int jt = j << tsh;
            float2 w1 = tw[jt], w2 = tw[2*jt], w3 = cmul(w1, w2);
            s[base]     = cadd(t0, t2);
            s[base+q]   = cmul(cadd(t1, t3), w1);
            s[base+2*q] = cmul(csub(t0, t2), w2);
            s[base+3*q] = cmul(csub(t1, t3), w3);
        }
        __syncthreads();
    }

    for (int p = tid; p < 4096; p += 512) {
        unsigned rb = __brev((unsigned)p) >> 20;
        int k = (int)(((rb & 0x555u) << 1) | ((rb >> 1) & 0x555u));
        if (!(k <= fl || k >= 4096 - fl)) s[p] = make_float2(0.f, 0.f);
    }
    __syncthreads();

    for (int logq = 0; logq <= 10; logq += 2) {
        int q = 1 << logq;
        int tsh = 10 - logq;
        #pragma unroll
        for (int pp = 0; pp < 2; pp++) {
            int p = tid + pp*512;
            int j = p & (q - 1);
            int base = ((p >> logq) << (logq + 2)) | j;
            int jt = j << tsh;
            float2 w1 = tw[jt], w2 = tw[2*jt], w3 = cmul(w1, w2);
            float2 a = s[base];
            float2 b = cmulc(s[base+q],   w1);
            float2 c = cmulc(s[base+2*q], w2);
            float2 d = cmulc(s[base+3*q], w3);
            float2 t0 = cadd(a, c), t1 = csub(a, c);
            float2 t2 = cadd(b, d), t3 = mulposi(csub(b, d));
            s[base]     = cadd(t0, t2);
            s[base+q]   = cadd(t1, t3);
            s[base+2*q] = csub(t0, t2);
            s[base+3*q] = csub(t1, t3);
        }
        __syncthreads();
    }

    float* y0 = g_zf + roff;
    float* y1 = y0 + T;
    const float scl = 1.0f / 4096.0f;
    for (int i = tid; i < 4096; i += 512) {
        float2 v = s[i];
        y0[i] = v.x * scl;
        y1[i] = v.y * scl;
    }
}

// ------------------------ in_proj (f32x2) + inv2 ------------------------
// block 64c x 128t, 256 threads; thread = 8c x 4t (2 t-pairs). Also emits g_inv2.
__global__ __launch_bounds__(256) void in_proj_kernel(int sc, int use_zf, const float* __restrict__ b_in)
{
    __shared__ float zsm[32][128];   // 16KB
    __shared__ float wsm[32][64];    // 8KB
    __shared__ float red[128][8];    // 4KB
    const float* src = use_zf ? g_zf : g_residual;
    int b = blockIdx.y, t0 = blockIdx.x * 128;
    int tid = threadIdx.x;
    int tx = tid & 31, ty = tid >> 5;   // warp == ty (c-group)

    unsigned long long acc[8][2];
    #pragma unroll
    for (int i = 0; i < 8; i++) { acc[i][0] = 0ull; acc[i][1] = 0ull; }

    for (int d0 = 0; d0 < D; d0 += 32) {
        for (int i = tid; i < 32*128; i += 256) {
            int dd = i >> 7, tt = i & 127;
            zsm[dd][tt] = src[((size_t)(b*D + d0 + dd))*T + t0 + tt];
        }
        for (int i = tid; i < 32*64; i += 256) {
            int dd = i >> 6, c = i & 63;
            wsm[dd][c] = g_WiT[((size_t)sc*512 + d0 + dd)*64 + c];
        }
        __syncthreads();
        #pragma unroll 8
        for (int dd = 0; dd < 32; dd++) {
            ulonglong2 z2 = *(const ulonglong2*)&zsm[dd][4*tx];
            float4 wa = *(const float4*)&wsm[dd][8*ty];
            float4 wb = *(const float4*)&wsm[dd][8*ty + 4];
            unsigned long long w0 = packf2(wa.x, wa.x), w1 = packf2(wa.y, wa.y);
            unsigned long long w2 = packf2(wa.z, wa.z), w3 = packf2(wa.w, wa.w);
            unsigned long long w4 = packf2(wb.x, wb.x), w5 = packf2(wb.y, wb.y);
            unsigned long long w6 = packf2(wb.z, wb.z), w7 = packf2(wb.w, wb.w);
            fma2(acc[0][0], w0, z2.x); fma2(acc[0][1], w0, z2.y);
            fma2(acc[1][0], w1, z2.x); fma2(acc[1][1], w1, z2.y);
            fma2(acc[2][0], w2, z2.x); fma2(acc[2][1], w2, z2.y);
            fma2(acc[3][0], w3, z2.x); fma2(acc[3][1], w3, z2.y);
            fma2(acc[4][0], w4, z2.x); fma2(acc[4][1], w4, z2.y);
            fma2(acc[5][0], w5, z2.x); fma2(acc[5][1], w5, z2.y);
            fma2(acc[6][0], w6, z2.x); fma2(acc[6][1], w6, z2.y);
            fma2(acc[7][0], w7, z2.x); fma2(acc[7][1], w7, z2.y);
        }
        __syncthreads();
    }

    float ss0 = 0.f, ss1 = 0.f, ss2 = 0.f, ss3 = 0.f;
    #pragma unroll
    for (int cc = 0; cc < 8; cc++) {
        int c = 8*ty + cc;
        float bb = b_in[sc*CD + c];
        float2 v0 = unpackf2(acc[cc][0]);
        float2 v1 = unpackf2(acc[cc][1]);
        float4 st = make_float4(v0.x + bb, v0.y + bb, v1.x + bb, v1.y + bb);
        *(float4*)&g_ze[((size_t)(b*CD + c))*T + t0 + 4*tx] = st;
        ss0 = fmaf(st.x, st.x, ss0);
        ss1 = fmaf(st.y, st.y, ss1);
        ss2 = fmaf(st.z, st.z, ss2);
        ss3 = fmaf(st.w, st.w, ss3);
    }
    red[4*tx + 0][ty] = ss0;
    red[4*tx + 1][ty] = ss1;
    red[4*tx + 2][ty] = ss2;
    red[4*tx + 3][ty] = ss3;
    __syncthreads();
    if (tid < 128) {
        float s = 0.f;
        #pragma unroll
        for (int w = 0; w < 8; w++) s += red[tid][w];
        g_inv2[b*T + t0 + tid] = 2.0f / fmaxf(sqrtf(s), 1e-12f);
    }
}

// ------------------------ nearest-code argmax (f32x2 register-tiled) ------------------------
// block 128t x 64j; 128 threads; thread = 4t x 16j. grid (32, B, NSPLIT).
__global__ __launch_bounds__(128) void argmax_kernel(int sc)
{
    __shared__ float zs[64][128];            // 32KB (reused for reduction)
    __shared__ ulonglong2 ws[2][64][8];      // 16KB
    int b = blockIdx.y, split = blockIdx.z;
    int t0 = blockIdx.x * 128;
    int tid = threadIdx.x;
    int tx = tid & 31, ty = tid >> 5;        // warp == ty (j-group)

    for (int i = tid; i < 64*128; i += 128) {
        int c = i >> 7, tt = i & 127;
        zs[c][tt] = g_ze[((size_t)(b*CD + c))*T + t0 + tt];
    }
    {
        const float4* p = (const float4*)(g_cnp + (size_t)(sc*32 + split*2)*2048);
        float4* wdst = (float4*)ws;
        for (int l = tid; l < 1024; l += 128) wdst[l] = p[l];
    }
    __syncthreads();

    int jt = ty >> 1;
    int qh = (ty & 1) * 4;
    unsigned long long acc[4][8];
    #pragma unroll
    for (int i = 0; i < 4; i++)
        #pragma unroll
        for (int m = 0; m < 8; m++) acc[i][m] = 0ull;

    #pragma unroll 4
    for (int c = 0; c < 64; c++) {
        float4 zf = *(const float4*)&zs[c][4*tx];
        unsigned long long zz0 = packf2(zf.x, zf.x);
        unsigned long long zz1 = packf2(zf.y, zf.y);
        unsigned long long zz2 = packf2(zf.z, zf.z);
        unsigned long long zz3 = packf2(zf.w, zf.w);
        #pragma unroll
        for (int q = 0; q < 4; q++) {
            ulonglong2 w = ws[jt][c][qh + q];
            fma2(acc[0][2*q], w.x, zz0); fma2(acc[0][2*q+1], w.y, zz0);
            fma2(acc[1][2*q], w.x, zz1); fma2(acc[1][2*q+1], w.y, zz1);
            fma2(acc[2][2*q], w.x, zz2); fma2(acc[2][2*q+1], w.y, zz2);
            fma2(acc[3][2*q], w.x, zz3); fma2(acc[3][2*q+1], w.y, zz3);
        }
    }

    float iv[4];
    #pragma unroll
    for (int i = 0; i < 4; i++) iv[i] = g_inv2[b*T + t0 + 4*tx + i];

    int jbase = split*64 + jt*32 + qh*4;     // global j of this thread's first code
    const float* cnn = g_cnn + sc*CS + jbase;
    float best[4]; int bi[4];
    #pragma unroll
    for (int i = 0; i < 4; i++) { best[i] = -INFINITY; bi[i] = 0; }

    #pragma unroll
    for (int q = 0; q < 4; q++) {
        float n0 = cnn[4*q + 0], n1 = cnn[4*q + 1], n2 = cnn[4*q + 2], n3 = cnn[4*q + 3];
        #pragma unroll
        for (int i = 0; i < 4; i++) {
            float2 d0 = unpackf2(acc[i][2*q]);
            float2 d1 = unpackf2(acc[i][2*q+1]);
            float s0 = fmaf(d0.x, iv[i], -n0);
            float s1 = fmaf(d0.y, iv[i], -n1);
            float s2 = fmaf(d1.x, iv[i], -n2);
            float s3 = fmaf(d1.y, iv[i], -n3);
            int j0 = jbase + 4*q;
            if (s0 > best[i]) { best[i] = s0; bi[i] = j0; }
            if (s1 > best[i]) { best[i] = s1; bi[i] = j0 + 1; }
            if (s2 > best[i]) { best[i] = s2; bi[i] = j0 + 2; }
            if (s3 > best[i]) { best[i] = s3; bi[i] = j0 + 3; }
        }
    }

    __syncthreads();
    float* rb = &zs[0][0];            // [128][4]
    int*   ri = (int*)&zs[16][0];     // [128][4]
    #pragma unroll
    for (int i = 0; i < 4; i++) {
        rb[(4*tx + i)*4 + ty] = best[i];
        ri[(4*tx + i)*4 + ty] = bi[i];
    }
    __syncthreads();
    if (tid < 128) {
        float bv = -INFINITY; int bj = 0;
        #pragma unroll
        for (int k = 0; k < 4; k++) {          // ty ascending == j ascending
            float v = rb[tid*4 + k];
            int ix = ri[tid*4 + k];
            if (v > bv) { bv = v; bj = ix; }
        }
        size_t gi = (size_t)split*BT + b*T + t0 + tid;
        g_pbest[gi] = bv;
        g_pidx[gi]  = bj;
    }
}

// ------------------------ split-combine + loss + out_proj + residual ------------------------
// block 128t, 256 threads; thread = 8d x 4t per 64-d chunk.
__global__ __launch_bounds__(256) void loss_outproj_kernel(int sc, int mode,
    const float* __restrict__ cb_s, const float* __restrict__ b_out_s,
    const float* __restrict__ z, float* __restrict__ zq_out, float* __restrict__ codes_out)
{
    __shared__ float cbs[64][128];     // 32KB, XOR-swizzled columns
    __shared__ float wpool[64*64];     // 16KB; start aliased by scodes + red
    int* scodes = (int*)wpool;         // [128]
    float* redp = wpool + 128;         // [8]
    int b = blockIdx.y, t0 = blockIdx.x * 128;
    int tid = threadIdx.x;
    int tx = tid & 31, ty = tid >> 5;  // warp == ty (d-group)

    // combine argmax splits -> final codes (ascending split = ascending j tie-break)
    if (tid < 128) {
        int gi = b*T + t0 + tid;
        float bv = -INFINITY; int bj = 0;
        #pragma unroll
        for (int sp = 0; sp < NSPLIT; sp++) {
            float v = g_pbest[(size_t)sp*BT + gi];
            int ix = g_pidx[(size_t)sp*BT + gi];
            if (v > bv) { bv = v; bj = ix; }
        }
        scodes[tid] = bj;
        if (codes_out) codes_out[((size_t)(b*NSCALES + sc))*T + t0 + tid] = (float)bj;
    }
    __syncthreads();

    // gather codebook rows into swizzled smem
    for (int i = tid; i < 64*128; i += 256) {
        int tt = i >> 6, c = i & 63;
        cbs[c][tt ^ ((c & 31) << 2)] = cb_s[scodes[tt]*64 + c];
    }
    __syncthreads();

    // loss: sum (z_e - cb)^2
    float ls = 0.f;
    for (int i = tid; i < 64*128; i += 256) {
        int c = i >> 7, tt = i & 127;
        float d = g_ze[((size_t)(b*CD + c))*T + t0 + tt] - cbs[c][tt ^ ((c & 31) << 2)];
        ls = fmaf(d, d, ls);
    }
    #pragma unroll
    for (int o = 16; o; o >>= 1) ls += __shfl_xor_sync(~0u, ls, o);
    if ((tid & 31) == 0) redp[tid >> 5] = ls;
    __syncthreads();
    if (tid == 0) {
        float tot = 0.f;
        #pragma unroll
        for (int w = 0; w < 8; w++) tot += redp[w];
        g_partials[sc*256 + b*32 + blockIdx.x] = tot;
    }

    // out_proj
    for (int d0 = 0; d0 < D; d0 += 64) {
        __syncthreads();
        for (int i = tid; i < 64*64; i += 256) {
            int c = i >> 6, dd = i & 63;
            wpool[c*64 + dd] = g_WoT[((size_t)sc*64 + c)*512 + d0 + dd];
        }
        __syncthreads();

        unsigned long long acc[8][2];
        #pragma unroll
        for (int i = 0; i < 8; i++) { acc[i][0] = 0ull; acc[i][1] = 0ull; }
        #pragma unroll 8
        for (int c = 0; c < 64; c++) {
            ulonglong2 cb2 = *(const ulonglong2*)&cbs[c][(4*tx) ^ ((c & 31) << 2)];
            float4 wa = *(const float4*)&wpool[c*64 + 8*ty];
            float4 wb = *(const float4*)&wpool[c*64 + 8*ty + 4];
            unsigned long long w0 = packf2(wa.x, wa.x), w1 = packf2(wa.y, wa.y);
            unsigned long long w2 = packf2(wa.z, wa.z), w3 = packf2(wa.w, wa.w);
            unsigned long long w4 = packf2(wb.x, wb.x), w5 = packf2(wb.y, wb.y);
            unsigned long long w6 = packf2(wb.z, wb.z), w7 = packf2(wb.w, wb.w);
            fma2(acc[0][0], w0, cb2.x); fma2(acc[0][1], w0, cb2.y);
            fma2(acc[1][0], w1, cb2.x); fma2(acc[1][1], w1, cb2.y);
            fma2(acc[2][0], w2, cb2.x); fma2(acc[2][1], w2, cb2.y);
            fma2(acc[3][0], w3, cb2.x); fma2(acc[3][1], w3, cb2.y);
            fma2(acc[4][0], w4, cb2.x); fma2(acc[4][1], w4, cb2.y);
            fma2(acc[5][0], w5, cb2.x); fma2(acc[5][1], w5, cb2.y);
            fma2(acc[6][0], w6, cb2.x); fma2(acc[6][1], w6, cb2.y);
            fma2(acc[7][0], w7, cb2.x); fma2(acc[7][1], w7, cb2.y);
        }

        #pragma unroll
        for (int k = 0; k < 8; k++) {
            int d = d0 + 8*ty + k;
            float bb = b_out_s[d];
            float2 u0 = unpackf2(acc[k][0]);
            float2 u1 = unpackf2(acc[k][1]);
            float4 v = make_float4(u0.x + bb, u0.y + bb, u1.x + bb, u1.y + bb);
            size_t base = ((size_t)(b*D + d))*T + t0 + 4*tx;
            if (mode == 0) {
                float4 zv = *(const float4*)&z[base];
                float4 r = make_float4(zv.x - v.x, zv.y - v.y, zv.z - v.z, zv.w - v.w);
                *(float4*)&g_residual[base] = r;
            } else if (mode == 1) {
                float4 r = *(const float4*)&g_residual[base];
                r.x -= v.x; r.y -= v.y; r.z -= v.z; r.w -= v.w;
                *(float4*)&g_residual[base] = r;
            } else {
                float4 zv = *(const float4*)&z[base];
                float4 r = *(const float4*)&g_residual[base];
                float4 o = make_float4(zv.x - r.x + v.x, zv.y - r.y + v.y,
                                       zv.z - r.z + v.z, zv.w - r.w + v.w);
                *(float4*)&zq_out[base] = o;
            }
        }
    }
}

// ------------------------ final loss reduce ------------------------
__global__ void reduce_loss_kernel(float* __restrict__ out_loss)
{
    __shared__ float s[1024];
    int tid = threadIdx.x;
    float v = 0.f;
    for (int i = tid; i < NSCALES*256; i += 1024) v += g_partials[i];
    s[tid] = v;
    __syncthreads();
    for (int h = 512; h; h >>= 1) {
        if (tid < h) s[tid] += s[tid + h];
        __syncthreads();
    }
    if (tid == 0) {
        float m = s[0] / LOSS_MEAN_DENOM;
        out_loss[0] = m;
        out_loss[1] = m;
    }
}

// ------------------------ launch ------------------------
extern "C" void kernel_launch(void* const* d_in, const int* in_sizes, int n_in,
                              void* d_out, int out_size)
{
    const float* z     = (const float*)d_in[0];
    const float* v_in  = (const float*)d_in[1];
    const float* g_in  = (const float*)d_in[2];
    const float* b_in  = (const float*)d_in[3];
    const float* cb    = (const float*)d_in[4];
    const float* v_out = (const float*)d_in[5];
    const float* g_out = (const float*)d_in[6];
    const float* b_out = (const float*)d_in[7];
    float* out = (float*)d_out;

    bool full = out_size >= (LOSS_OFF + 2);
    float* codes_out = full ? (out + ZQ_ELEMS) : nullptr;

    prep_weights_kernel<<<NSCALES*1600, 128>>>(v_in, g_in, v_out, g_out, cb);

    const int scales[NSCALES] = {4, 2, 1, 1};
    for (int i = 0; i < NSCALES; i++) {
        int s = scales[i];
        int use_zf = (s > 1) ? 1 : 0;
        if (use_zf) {
            int fl = 2049 / s;
            fft_filter_kernel<<<NROWS/2, 512>>>(z, (i == 0) ? 1 : 0, fl);
        }
        in_proj_kernel<<<dim3(T/128, B), 256>>>(i, use_zf, b_in);
        argmax_kernel<<<dim3(T/128, B, NSPLIT), 128>>>(i);
        int mode = (i == 0) ? 0 : ((i == NSCALES-1) ? 2 : 1);
        loss_outproj_kernel<<<dim3(T/128, B), 256>>>(i, mode, cb + (size_t)i*CS*CD,
                                                     b_out + i*D, z, out, codes_out);
    }
    if (full) reduce_loss_kernel<<<1, 1024>>>(out + LOSS_OFF);
}